// round 10
// baseline (speedup 1.0000x reference)
#include <cuda_runtime.h>
#include <math.h>
#include <stdint.h>

#define T_TOK 4096
#define H_DIM 2048
#define I_DIM 2048
#define E_NUM 16

#define BM 128
#define BN 128
#define PI8 48                        // int8 smem row pitch (32B data + 16B pad)
#define TI8 (BM * PI8)                // 6144 bytes per tile

#define MAX_SLOTS (T_TOK * 2 + E_NUM * BM)   // 10240
#define M_TILES   (MAX_SLOTS / BM)           // 80

#define DYN1 (4 * TI8 + 2 * 128 * 4 + 256 * 64 * 4)   // 91136
#define DYN2 (4 * TI8 + 2 * 128 * 4)                   // 25600

// ---------------- scratch ---------------------------------------------------
__device__ int   g_slot_token[MAX_SLOTS];
__device__ int   g_tile_expert[M_TILES];
__device__ int   g_counts[E_NUM];
__device__ int   g_cursor[E_NUM];
__device__ int   g_seg_start[E_NUM];
__device__ int   g_tok_eid[T_TOK * 2];
__device__ int   g_tok_slot[T_TOK * 2];
__device__ float g_tok_w[T_TOK * 2];

__device__ float g_h[(size_t)MAX_SLOTS * I_DIM];
__device__ float g_y[(size_t)MAX_SLOTS * H_DIM];

// quantized operands (2-level residual int8)
__device__ uint8_t g_xq1[(size_t)T_TOK * H_DIM],   g_xq2[(size_t)T_TOK * H_DIM];
__device__ uint8_t g_wq1[(size_t)E_NUM * 2 * I_DIM * H_DIM];
__device__ uint8_t g_wq2[(size_t)E_NUM * 2 * I_DIM * H_DIM];
__device__ uint8_t g_w2q1[(size_t)E_NUM * H_DIM * I_DIM];
__device__ uint8_t g_w2q2[(size_t)E_NUM * H_DIM * I_DIM];
__device__ uint8_t g_hq1[(size_t)MAX_SLOTS * I_DIM], g_hq2[(size_t)MAX_SLOTS * I_DIM];
__device__ float g_sx[T_TOK];
__device__ float g_sh[MAX_SLOTS];
__device__ float g_sw1[E_NUM * 2 * I_DIM];
__device__ float g_sw2[E_NUM * H_DIM];

// ---------------- helpers ---------------------------------------------------
__device__ __forceinline__ uint32_t smem_u32(const void* p) {
    uint32_t a;
    asm("{ .reg .u64 t; cvta.to.shared.u64 t, %1; cvt.u32.u64 %0, t; }" : "=r"(a) : "l"(p));
    return a;
}

#define LDSM4(R, A)                                                             \
    asm volatile("ldmatrix.sync.aligned.m8n8.x4.shared.b16 {%0,%1,%2,%3}, [%4];" \
        : "=r"((R)[0]), "=r"((R)[1]), "=r"((R)[2]), "=r"((R)[3]) : "r"(A))

__device__ __forceinline__ void mma_s8(int* d, const uint32_t* a, const uint32_t* b) {
    asm volatile("mma.sync.aligned.m16n8k32.row.col.s32.s8.s8.s32 "
        "{%0,%1,%2,%3}, {%4,%5,%6,%7}, {%8,%9}, {%0,%1,%2,%3};"
        : "+r"(d[0]), "+r"(d[1]), "+r"(d[2]), "+r"(d[3])
        : "r"(a[0]), "r"(a[1]), "r"(a[2]), "r"(a[3]), "r"(b[0]), "r"(b[1]));
}

// ---------------- 2-level row quantization (rows of 2048) -------------------
__device__ __forceinline__ uint32_t packb(float f0, float f1, float f2, float f3) {
    uint32_t t0 = __byte_perm(__float_as_uint(f0), __float_as_uint(f1), 0x0040);
    uint32_t t1 = __byte_perm(__float_as_uint(f2), __float_as_uint(f3), 0x0040);
    return __byte_perm(t0, t1, 0x5410);
}

__device__ __forceinline__ void q2w(float4 v, float inv, uint32_t& w1, uint32_t& w2) {
    const float MG = 12582912.f;   // 2^23 + 2^22
    float t0 = fmaf(v.x, inv, MG), t1 = fmaf(v.y, inv, MG);
    float t2 = fmaf(v.z, inv, MG), t3 = fmaf(v.w, inv, MG);
    w1 = packb(t0, t1, t2, t3);
    float q0 = t0 - MG, q1 = t1 - MG, q2 = t2 - MG, q3 = t3 - MG;
    float r0 = fmaf(v.x, inv, -q0) * 254.f + MG;
    float r1 = fmaf(v.y, inv, -q1) * 254.f + MG;
    float r2 = fmaf(v.z, inv, -q2) * 254.f + MG;
    float r3 = fmaf(v.w, inv, -q3) * 254.f + MG;
    w2 = packb(r0, r1, r2, r3);
}

// mode: 0 = x -> g_xq*, 1 = ws -> g_wq*, 2 = w2s -> g_w2q*, 3 = g_h -> g_hq*
// (device globals are resolved IN DEVICE CODE; passing them as host-side
//  kernel args was the R9 bug)
__global__ void __launch_bounds__(256) k_quant(const float* __restrict__ src, int mode) {
    const int row = blockIdx.x;
    const int tid = threadIdx.x;

    uint8_t* q1;  uint8_t* q2;  float* sc;  const float* s;
    if (mode == 0)      { q1 = g_xq1;  q2 = g_xq2;  sc = g_sx;  s = src; }
    else if (mode == 1) { q1 = g_wq1;  q2 = g_wq2;  sc = g_sw1; s = src; }
    else if (mode == 2) { q1 = g_w2q1; q2 = g_w2q2; sc = g_sw2; s = src; }
    else                { q1 = g_hq1;  q2 = g_hq2;  sc = g_sh;  s = g_h; }

    const float4* r4 = (const float4*)(s + (size_t)row * 2048);
    float4 v0 = r4[tid * 2], v1 = r4[tid * 2 + 1];
    float m = fmaxf(fmaxf(fmaxf(fabsf(v0.x), fabsf(v0.y)), fmaxf(fabsf(v0.z), fabsf(v0.w))),
                    fmaxf(fmaxf(fabsf(v1.x), fabsf(v1.y)), fmaxf(fabsf(v1.z), fabsf(v1.w))));
    #pragma unroll
    for (int o = 16; o; o >>= 1) m = fmaxf(m, __shfl_xor_sync(0xffffffffu, m, o));
    __shared__ float wred[8];
    __shared__ float Msh;
    if ((tid & 31) == 0) wred[tid >> 5] = m;
    __syncthreads();
    if (tid == 0) {
        float M = wred[0];
        #pragma unroll
        for (int i = 1; i < 8; i++) M = fmaxf(M, wred[i]);
        Msh = M;
        sc[row] = M * (1.f / 127.f);
    }
    __syncthreads();
    float M = Msh;
    float inv = M > 0.f ? 127.f / M : 0.f;
    uint32_t* o1 = (uint32_t*)(q1 + (size_t)row * 2048);
    uint32_t* o2 = (uint32_t*)(q2 + (size_t)row * 2048);
    uint32_t a, b;
    q2w(v0, inv, a, b); o1[tid * 2 + 0] = a; o2[tid * 2 + 0] = b;
    q2w(v1, inv, a, b); o1[tid * 2 + 1] = a; o2[tid * 2 + 1] = b;
}

// ---------------- routing / bookkeeping -------------------------------------
__global__ void k_init() {
    int i = blockIdx.x * blockDim.x + threadIdx.x;
    if (i < MAX_SLOTS) g_slot_token[i] = -1;
    if (i < E_NUM) { g_counts[i] = 0; g_cursor[i] = 0; }
}

__global__ void __launch_bounds__(512) k_route(const float* __restrict__ x,
                                               const float* __restrict__ gw) {
    int t = blockIdx.x, warp = threadIdx.x >> 5, lane = threadIdx.x & 31;
    const float* xr = x + (size_t)t * H_DIM;
    const float* gr = gw + (size_t)warp * H_DIM;
    float s = 0.f;
    for (int k = lane; k < H_DIM; k += 32) s += xr[k] * gr[k];
    #pragma unroll
    for (int o = 16; o; o >>= 1) s += __shfl_xor_sync(0xffffffffu, s, o);
    __shared__ float logits[E_NUM];
    if (lane == 0) logits[warp] = s;
    __syncthreads();
    if (threadIdx.x == 0) {
        int i0 = -1, i1 = -1; float v0 = -1e30f, v1 = -1e30f;
        #pragma unroll
        for (int e = 0; e < E_NUM; e++) {
            float v = logits[e];
            if (v > v0) { v1 = v0; i1 = i0; v0 = v; i0 = e; }
            else if (v > v1) { v1 = v; i1 = e; }
        }
        float e1 = expf(v1 - v0);
        float w0 = 1.f / (1.f + e1);
        g_tok_eid[t * 2 + 0] = i0;  g_tok_eid[t * 2 + 1] = i1;
        g_tok_w [t * 2 + 0] = w0;  g_tok_w [t * 2 + 1] = e1 * w0;
        atomicAdd(&g_counts[i0], 1);
        atomicAdd(&g_counts[i1], 1);
    }
}

__global__ void k_offsets() {
    if (threadIdx.x == 0 && blockIdx.x == 0) {
        int run = 0;
        for (int e = 0; e < E_NUM; e++) {
            g_seg_start[e] = run;
            int padded = (g_counts[e] + BM - 1) / BM * BM;
            for (int tt = run / BM; tt < (run + padded) / BM; tt++) g_tile_expert[tt] = e;
            run += padded;
        }
        for (int tt = run / BM; tt < M_TILES; tt++) g_tile_expert[tt] = -1;
    }
}

__global__ void k_scatter() {
    int t = blockIdx.x * blockDim.x + threadIdx.x;
    if (t >= T_TOK) return;
    #pragma unroll
    for (int k = 0; k < 2; k++) {
        int e = g_tok_eid[t * 2 + k];
        int pos = atomicAdd(&g_cursor[e], 1);
        int slot = g_seg_start[e] + pos;
        g_slot_token[slot] = t;
        g_tok_slot[t * 2 + k] = slot;
    }
}

// ---------------- int8 mainloop: one K=2048 pass of 128x128 -----------------
__device__ __forceinline__ void i8_pass(const uint8_t* a1p, const uint8_t* a2p,
                                        const uint8_t* b1p, const uint8_t* b2p,
                                        char* sm, uint32_t uB,
                                        int lrow, int half, int wm, int wn, int lane,
                                        int (*accM)[4][4], int (*accC)[4][4]) {
    constexpr int NCH = 64;
    uint4 va1 = *(const uint4*)(a1p + half * 16);
    uint4 va2 = *(const uint4*)(a2p + half * 16);
    uint4 vb1 = *(const uint4*)(b1p + half * 16);
    uint4 vb2 = *(const uint4*)(b2p + half * 16);
    const uint32_t so = (uint32_t)(lrow * PI8 + half * 16);
    *(uint4*)(sm + so) = va1;
    *(uint4*)(sm + TI8 + so) = va2;
    *(uint4*)(sm + 2 * TI8 + so) = vb1;
    *(uint4*)(sm + 3 * TI8 + so) = vb2;
    __syncthreads();

    for (int ic = 0; ic < NCH; ic++) {
        if (ic + 1 < NCH) {
            const int kb = (ic + 1) * 32;
            va1 = *(const uint4*)(a1p + kb + half * 16);
            va2 = *(const uint4*)(a2p + kb + half * 16);
            vb1 = *(const uint4*)(b1p + kb + half * 16);
            vb2 = *(const uint4*)(b2p + kb + half * 16);
        }
        uint32_t A1[4][4], A2[4][4];
        #pragma unroll
        for (int i = 0; i < 4; i++) {
            uint32_t ad = uB + (uint32_t)((wm * 64 + i * 16 + (lane & 15)) * PI8
                                          + (lane >> 4) * 16);
            LDSM4(A1[i], ad);
            LDSM4(A2[i], ad + TI8);
        }
        uint32_t B1[8], B2[8];
        #pragma unroll
        for (int p = 0; p < 2; p++) {
            uint32_t bd = uB + 2 * TI8
                        + (uint32_t)((wn * 32 + p * 16 + (lane & 7) + ((lane >> 4) << 3)) * PI8
                                     + ((lane >> 3) & 1) * 16);
            LDSM4(&B1[p * 4], bd);
            LDSM4(&B2[p * 4], bd + TI8);
        }
        #pragma unroll
        for (int i = 0; i < 4; i++)
            #pragma unroll
            for (int j = 0; j < 4; j++) {
                const uint32_t* b1 = &B1[(j >> 1) * 4 + (j & 1) * 2];
                const uint32_t* b2 = &B2[(j >> 1) * 4 + (j & 1) * 2];
                mma_s8(accM[i][j], A1[i], b1);
                mma_s8(accC[i][j], A1[i], b2);
                mma_s8(accC[i][j], A2[i], b1);
            }
        __syncthreads();
        if (ic + 1 < NCH) {
            *(uint4*)(sm + so) = va1;
            *(uint4*)(sm + TI8 + so) = va2;
            *(uint4*)(sm + 2 * TI8 + so) = vb1;
            *(uint4*)(sm + 3 * TI8 + so) = vb2;
            __syncthreads();
        }
    }
}

// ---------------- GEMM1 fused: h = silu(x@Wg^T) * (x@Wu^T) ------------------
__global__ void __launch_bounds__(256, 1) k_gemm1_i8() {
    const int mt = blockIdx.y, nt = blockIdx.x;
    const int e = g_tile_expert[mt];
    if (e < 0) return;
    extern __shared__ __align__(128) char sm[];
    float* sa_s = (float*)(sm + 4 * TI8);
    float* sb_s = sa_s + 128;
    float* stash = sb_s + 128;

    const int tid = threadIdx.x, lane = tid & 31, wid = tid >> 5;
    const int wm = wid & 1, wn = wid >> 1;
    const int lrow = tid >> 1, half = tid & 1;

    int tokr = g_slot_token[mt * BM + lrow];
    if (tokr < 0) tokr = 0;                       // dead rows: results unused
    const uint8_t* a1p = g_xq1 + (size_t)tokr * 2048;
    const uint8_t* a2p = g_xq2 + (size_t)tokr * 2048;
    if (tid < 128) {
        int tk = g_slot_token[mt * BM + tid];
        sa_s[tid] = tk >= 0 ? g_sx[tk] : 0.f;
        sb_s[tid] = g_sw1[(size_t)e * 4096 + nt * BN + tid];
    }
    const uint32_t uB = smem_u32(sm);

    int accM[4][4][4], accC[4][4][4];
    #pragma unroll
    for (int i = 0; i < 4; i++)
        #pragma unroll
        for (int j = 0; j < 4; j++)
            #pragma unroll
            for (int q = 0; q < 4; q++) { accM[i][j][q] = 0; accC[i][j][q] = 0; }

    // pass 0: gate
    {
        const uint8_t* b1p = g_wq1 + ((size_t)e * 4096 + nt * BN + lrow) * 2048;
        const uint8_t* b2p = g_wq2 + ((size_t)e * 4096 + nt * BN + lrow) * 2048;
        i8_pass(a1p, a2p, b1p, b2p, sm, uB, lrow, half, wm, wn, lane, accM, accC);
    }
    {
        float* st = stash + tid * 64;
        #pragma unroll
        for (int i = 0; i < 4; i++) {
            int rl0 = wm * 64 + i * 16 + (lane >> 2);
            #pragma unroll
            for (int j = 0; j < 4; j++) {
                int cl0 = wn * 32 + j * 8 + 2 * (lane & 3);
                #pragma unroll
                for (int q = 0; q < 4; q++) {
                    int rl = rl0 + (q >> 1) * 8;
                    int cl = cl0 + (q & 1);
                    st[(i * 4 + j) * 4 + q] = sa_s[rl] * sb_s[cl] *
                        ((float)accM[i][j][q] + (float)accC[i][j][q] * (1.f / 254.f));
                }
            }
        }
    }
    __syncthreads();
    if (tid < 128) sb_s[tid] = g_sw1[(size_t)e * 4096 + 2048 + nt * BN + tid];

    #pragma unroll
    for (int i = 0; i < 4; i++)
        #pragma unroll
        for (int j = 0; j < 4; j++)
            #pragma unroll
            for (int q = 0; q < 4; q++) { accM[i][j][q] = 0; accC[i][j][q] = 0; }

    // pass 1: up
    {
        const uint8_t* b1p = g_wq1 + ((size_t)e * 4096 + 2048 + nt * BN + lrow) * 2048;
        const uint8_t* b2p = g_wq2 + ((size_t)e * 4096 + 2048 + nt * BN + lrow) * 2048;
        i8_pass(a1p, a2p, b1p, b2p, sm, uB, lrow, half, wm, wn, lane, accM, accC);
    }
    // epilogue: h = silu(g)*u
    {
        const float* st = stash + tid * 64;
        #pragma unroll
        for (int i = 0; i < 4; i++) {
            int rl0 = wm * 64 + i * 16 + (lane >> 2);
            #pragma unroll
            for (int j = 0; j < 4; j++) {
                int cl0 = wn * 32 + j * 8 + 2 * (lane & 3);
                #pragma unroll
                for (int q = 0; q < 4; q++) {
                    int rl = rl0 + (q >> 1) * 8;
                    int cl = cl0 + (q & 1);
                    float u = sa_s[rl] * sb_s[cl] *
                        ((float)accM[i][j][q] + (float)accC[i][j][q] * (1.f / 254.f));
                    float g = st[(i * 4 + j) * 4 + q];
                    g_h[(size_t)(mt * BM + rl) * I_DIM + nt * BN + cl] =
                        g / (1.f + __expf(-g)) * u;
                }
            }
        }
    }
}

// ---------------- GEMM2: y = h @ w2s[e]^T -----------------------------------
__global__ void __launch_bounds__(256, 1) k_gemm2_i8() {
    const int mt = blockIdx.y, nt = blockIdx.x;
    const int e = g_tile_expert[mt];
    if (e < 0) return;
    extern __shared__ __align__(128) char sm[];
    float* sa_s = (float*)(sm + 4 * TI8);
    float* sb_s = sa_s + 128;

    const int tid = threadIdx.x, lane = tid & 31, wid = tid >> 5;
    const int wm = wid & 1, wn = wid >> 1;
    const int lrow = tid >> 1, half = tid & 1;

    const uint8_t* a1p = g_hq1 + (size_t)(mt * BM + lrow) * 2048;
    const uint8_t* a2p = g_hq2 + (size_t)(mt * BM + lrow) * 2048;
    const uint8_t* b1p = g_w2q1 + ((size_t)e * 2048 + nt * BN + lrow) * 2048;
    const uint8_t* b2p = g_w2q2 + ((size_t)e * 2048 + nt * BN + lrow) * 2048;
    if (tid < 128) {
        sa_s[tid] = g_sh[mt * BM + tid];
        sb_s[tid] = g_sw2[(size_t)e * 2048 + nt * BN + tid];
    }
    const uint32_t uB = smem_u32(sm);

    int accM[4][4][4], accC[4][4][4];
    #pragma unroll
    for (int i = 0; i < 4; i++)
        #pragma unroll
        for (int j = 0; j < 4; j++)
            #pragma unroll
            for (int q = 0; q < 4; q++) { accM[i][j][q] = 0; accC[i][j][q] = 0; }

    i8_pass(a1p, a2p, b1p, b2p, sm, uB, lrow, half, wm, wn, lane, accM, accC);

    #pragma unroll
    for (int i = 0; i < 4; i++) {
        int rl0 = wm * 64 + i * 16 + (lane >> 2);
        #pragma unroll
        for (int j = 0; j < 4; j++) {
            int cl0 = wn * 32 + j * 8 + 2 * (lane & 3);
            #pragma unroll
            for (int q = 0; q < 4; q++) {
                int rl = rl0 + (q >> 1) * 8;
                int cl = cl0 + (q & 1);
                g_y[(size_t)(mt * BM + rl) * H_DIM + nt * BN + cl] =
                    sa_s[rl] * sb_s[cl] *
                    ((float)accM[i][j][q] + (float)accC[i][j][q] * (1.f / 254.f));
            }
        }
    }
}

// ---------------- combine ---------------------------------------------------
__global__ void k_combine(float* __restrict__ out) {
    int idx = blockIdx.x * blockDim.x + threadIdx.x;
    if (idx >= T_TOK * (H_DIM / 4)) return;
    int t = idx / (H_DIM / 4);
    int n = (idx % (H_DIM / 4)) * 4;
    int   s0 = g_tok_slot[t * 2 + 0], s1 = g_tok_slot[t * 2 + 1];
    float w0 = g_tok_w [t * 2 + 0], w1 = g_tok_w [t * 2 + 1];
    const float4 y0 = *(const float4*)&g_y[(size_t)s0 * H_DIM + n];
    const float4 y1 = *(const float4*)&g_y[(size_t)s1 * H_DIM + n];
    float4 o;
    o.x = w0 * y0.x + w1 * y1.x;
    o.y = w0 * y0.y + w1 * y1.y;
    o.z = w0 * y0.z + w1 * y1.z;
    o.w = w0 * y0.w + w1 * y1.w;
    *(float4*)&out[(size_t)t * H_DIM + n] = o;
}

// ---------------- launch ----------------------------------------------------
extern "C" void kernel_launch(void* const* d_in, const int* in_sizes, int n_in,
                              void* d_out, int out_size) {
    const float* x      = (const float*)d_in[0];
    const float* gate_w = (const float*)d_in[1];
    const float* ws     = (const float*)d_in[2];
    const float* w2s    = (const float*)d_in[3];
    float* out = (float*)d_out;

    cudaFuncSetAttribute(k_gemm1_i8, cudaFuncAttributeMaxDynamicSharedMemorySize, DYN1);
    cudaFuncSetAttribute(k_gemm2_i8, cudaFuncAttributeMaxDynamicSharedMemorySize, DYN2);

    k_init<<<(MAX_SLOTS + 255) / 256, 256>>>();
    k_route<<<T_TOK, 512>>>(x, gate_w);
    k_offsets<<<1, 32>>>();
    k_scatter<<<(T_TOK + 255) / 256, 256>>>();

    // quantize operands (destinations resolved in device code via mode)
    k_quant<<<T_TOK, 256>>>(x, 0);
    k_quant<<<E_NUM * 2 * I_DIM, 256>>>(ws, 1);
    k_quant<<<E_NUM * H_DIM, 256>>>(w2s, 2);

    k_gemm1_i8<<<dim3(I_DIM / BN, M_TILES), 256, DYN1>>>();
    k_quant<<<MAX_SLOTS, 256>>>((const float*)0, 3);
    k_gemm2_i8<<<dim3(H_DIM / BN, M_TILES), 256, DYN2>>>();
    k_combine<<<(T_TOK * (H_DIM / 4) + 255) / 256, 256>>>(out);
}

// round 11
// speedup vs baseline: 2.0539x; 2.0539x over previous
#include <cuda_runtime.h>
#include <cuda_bf16.h>
#include <math.h>
#include <stdint.h>

#define T_TOK 4096
#define H_DIM 2048
#define I_DIM 2048
#define E_NUM 16

#define BM 128
#define BN 128
#define KC 32
#define PITCH 80                      // bytes per smem row (32 bf16 + pad)
#define TILE_B (BM * PITCH)           // 10240
#define STAGE_B (4 * TILE_B)          // Ahi|Alo|Bhi|Blo = 40960
#define STASH_B (256 * 64 * 4)        // 65536
#define DYN1 (STAGE_B + STASH_B)      // 106496

#define MAX_SLOTS (T_TOK * 2 + E_NUM * BM)   // 10240
#define M_TILES   (MAX_SLOTS / BM)           // 80

// ---------------- scratch ---------------------------------------------------
__device__ int   g_slot_token[MAX_SLOTS];
__device__ int   g_tile_expert[M_TILES];
__device__ int   g_counts[E_NUM];
__device__ int   g_cursor[E_NUM];
__device__ int   g_seg_start[E_NUM];
__device__ int   g_tok_eid[T_TOK * 2];
__device__ int   g_tok_slot[T_TOK * 2];
__device__ float g_tok_w[T_TOK * 2];

__device__ float g_h[(size_t)MAX_SLOTS * I_DIM];
__device__ float g_y[(size_t)MAX_SLOTS * H_DIM];

// ---------------- helpers ---------------------------------------------------
__device__ __forceinline__ uint32_t smem_u32(const void* p) {
    uint32_t a;
    asm("{ .reg .u64 t; cvta.to.shared.u64 t, %1; cvt.u32.u64 %0, t; }" : "=r"(a) : "l"(p));
    return a;
}

#define LDSM4(R, A)                                                             \
    asm volatile("ldmatrix.sync.aligned.m8n8.x4.shared.b16 {%0,%1,%2,%3}, [%4];" \
        : "=r"((R)[0]), "=r"((R)[1]), "=r"((R)[2]), "=r"((R)[3]) : "r"(A))

__device__ __forceinline__ void mma_bf16(float* d, const uint32_t* a, const uint32_t* b) {
    asm volatile("mma.sync.aligned.m16n8k16.row.col.f32.bf16.bf16.f32 "
        "{%0,%1,%2,%3}, {%4,%5,%6,%7}, {%8,%9}, {%0,%1,%2,%3};"
        : "+f"(d[0]), "+f"(d[1]), "+f"(d[2]), "+f"(d[3])
        : "r"(a[0]), "r"(a[1]), "r"(a[2]), "r"(a[3]), "r"(b[0]), "r"(b[1]));
}

__device__ __forceinline__ void cvt_store(char* hi_t, char* lo_t, int row, int colf, float4 v) {
    __nv_bfloat162 h01 = __floats2bfloat162_rn(v.x, v.y);
    __nv_bfloat162 h23 = __floats2bfloat162_rn(v.z, v.w);
    float rx = v.x - __bfloat162float(h01.x);
    float ry = v.y - __bfloat162float(h01.y);
    float rz = v.z - __bfloat162float(h23.x);
    float rw = v.w - __bfloat162float(h23.y);
    __nv_bfloat162 l01 = __floats2bfloat162_rn(rx, ry);
    __nv_bfloat162 l23 = __floats2bfloat162_rn(rz, rw);
    uint32_t off = (uint32_t)(row * PITCH + colf * 2);
    *(uint2*)(hi_t + off) = make_uint2(*reinterpret_cast<uint32_t*>(&h01),
                                       *reinterpret_cast<uint32_t*>(&h23));
    *(uint2*)(lo_t + off) = make_uint2(*reinterpret_cast<uint32_t*>(&l01),
                                       *reinterpret_cast<uint32_t*>(&l23));
}

// ---------------- routing / bookkeeping -------------------------------------
__global__ void k_init() {
    int i = blockIdx.x * blockDim.x + threadIdx.x;
    if (i < MAX_SLOTS) g_slot_token[i] = -1;
    if (i < E_NUM) { g_counts[i] = 0; g_cursor[i] = 0; }
}

__global__ void __launch_bounds__(512) k_route(const float* __restrict__ x,
                                               const float* __restrict__ gw) {
    int t = blockIdx.x, warp = threadIdx.x >> 5, lane = threadIdx.x & 31;
    const float* xr = x + (size_t)t * H_DIM;
    const float* gr = gw + (size_t)warp * H_DIM;
    float s = 0.f;
    for (int k = lane; k < H_DIM; k += 32) s += xr[k] * gr[k];
    #pragma unroll
    for (int o = 16; o; o >>= 1) s += __shfl_xor_sync(0xffffffffu, s, o);
    __shared__ float logits[E_NUM];
    if (lane == 0) logits[warp] = s;
    __syncthreads();
    if (threadIdx.x == 0) {
        int i0 = -1, i1 = -1; float v0 = -1e30f, v1 = -1e30f;
        #pragma unroll
        for (int e = 0; e < E_NUM; e++) {
            float v = logits[e];
            if (v > v0) { v1 = v0; i1 = i0; v0 = v; i0 = e; }
            else if (v > v1) { v1 = v; i1 = e; }
        }
        float e1 = expf(v1 - v0);
        float w0 = 1.f / (1.f + e1);
        g_tok_eid[t * 2 + 0] = i0;  g_tok_eid[t * 2 + 1] = i1;
        g_tok_w [t * 2 + 0] = w0;  g_tok_w [t * 2 + 1] = e1 * w0;
        atomicAdd(&g_counts[i0], 1);
        atomicAdd(&g_counts[i1], 1);
    }
}

__global__ void k_offsets() {
    if (threadIdx.x == 0 && blockIdx.x == 0) {
        int run = 0;
        for (int e = 0; e < E_NUM; e++) {
            g_seg_start[e] = run;
            int padded = (g_counts[e] + BM - 1) / BM * BM;
            for (int tt = run / BM; tt < (run + padded) / BM; tt++) g_tile_expert[tt] = e;
            run += padded;
        }
        for (int tt = run / BM; tt < M_TILES; tt++) g_tile_expert[tt] = -1;
    }
}

__global__ void k_scatter() {
    int t = blockIdx.x * blockDim.x + threadIdx.x;
    if (t >= T_TOK) return;
    #pragma unroll
    for (int k = 0; k < 2; k++) {
        int e = g_tok_eid[t * 2 + k];
        int pos = atomicAdd(&g_cursor[e], 1);
        int slot = g_seg_start[e] + pos;
        g_slot_token[slot] = t;
        g_tok_slot[t * 2 + k] = slot;
    }
}

// ---------------- one K-pass, single-buffered, occupancy-2 ------------------
template <int K>
__device__ __forceinline__ void gemm_pass(const float* arow, const float* brow,
                                          char* sm, uint32_t uBase,
                                          int lrow, int lhal, int wm, int wn, int lane,
                                          float acc[4][4][4]) {
    constexpr int NCH = K / KC;
    for (int ic = 0; ic < NCH; ic++) {
        const int kb = ic * KC;
        // produce: LDG -> split-cvt -> STS (latency hidden by co-resident CTA)
        #pragma unroll
        for (int i = 0; i < 4; i++) {
            float4 va = arow ? *(const float4*)(arow + kb + lhal * 16 + i * 4)
                             : make_float4(0.f, 0.f, 0.f, 0.f);
            cvt_store(sm, sm + TILE_B, lrow, lhal * 16 + i * 4, va);
            float4 vb = *(const float4*)(brow + kb + lhal * 16 + i * 4);
            cvt_store(sm + 2 * TILE_B, sm + 3 * TILE_B, lrow, lhal * 16 + i * 4, vb);
        }
        __syncthreads();

        #pragma unroll
        for (int k16 = 0; k16 < 2; k16++) {
            uint32_t ahi[4][4], alo[4][4];
            #pragma unroll
            for (int i = 0; i < 4; i++) {
                uint32_t ad = uBase + (uint32_t)((wm * 64 + i * 16 + (lane & 15)) * PITCH
                                                 + k16 * 32 + (lane >> 4) * 16);
                LDSM4(ahi[i], ad);
                LDSM4(alo[i], ad + TILE_B);
            }
            uint32_t bhi[8], blo[8];
            #pragma unroll
            for (int p = 0; p < 2; p++) {
                uint32_t bd = uBase + (uint32_t)(2 * TILE_B)
                            + (uint32_t)((wn * 32 + p * 16 + (lane & 7) + ((lane >> 4) << 3)) * PITCH
                                         + k16 * 32 + ((lane >> 3) & 1) * 16);
                LDSM4(&bhi[p * 4], bd);
                LDSM4(&blo[p * 4], bd + TILE_B);
            }
            // term-major: maximal independent accumulator chains
            #pragma unroll
            for (int i = 0; i < 4; i++)
                #pragma unroll
                for (int j = 0; j < 4; j++)
                    mma_bf16(acc[i][j], ahi[i], &bhi[(j >> 1) * 4 + (j & 1) * 2]);
            #pragma unroll
            for (int i = 0; i < 4; i++)
                #pragma unroll
                for (int j = 0; j < 4; j++)
                    mma_bf16(acc[i][j], ahi[i], &blo[(j >> 1) * 4 + (j & 1) * 2]);
            #pragma unroll
            for (int i = 0; i < 4; i++)
                #pragma unroll
                for (int j = 0; j < 4; j++)
                    mma_bf16(acc[i][j], alo[i], &bhi[(j >> 1) * 4 + (j & 1) * 2]);
        }
        __syncthreads();
    }
}

// ---------------- GEMM1 fused: h = silu(x@Wg^T) * (x@Wu^T) ------------------
__global__ void __launch_bounds__(256, 2) k_gemm1(const float* __restrict__ X,
                                                  const float* __restrict__ Wall) {
    constexpr int K = H_DIM;
    const int mt = blockIdx.y, nt = blockIdx.x;
    const int expert = g_tile_expert[mt];
    if (expert < 0) return;
    const float* __restrict__ Wb = Wall + (size_t)expert * (2 * I_DIM) * K;

    extern __shared__ __align__(128) char sm[];
    float* stash = (float*)(sm + STAGE_B);

    const int tid = threadIdx.x, lane = tid & 31, wid = tid >> 5;
    const int wm = wid & 1, wn = wid >> 1;
    const int lrow = tid >> 1, lhal = tid & 1;

    int tok = g_slot_token[mt * BM + lrow];
    const float* arow = (tok >= 0) ? (X + (size_t)tok * K) : (const float*)0;
    const float* browG = Wb + (size_t)(nt * BN + lrow) * K;
    const float* browU = Wb + (size_t)(I_DIM + nt * BN + lrow) * K;

    const uint32_t uBase = smem_u32(sm);
    float acc[4][4][4];

    #pragma unroll
    for (int i = 0; i < 4; i++)
        #pragma unroll
        for (int j = 0; j < 4; j++)
            #pragma unroll
            for (int q = 0; q < 4; q++) acc[i][j][q] = 0.f;
    gemm_pass<K>(arow, browG, sm, uBase, lrow, lhal, wm, wn, lane, acc);
    {
        float* st = stash + tid * 64;
        #pragma unroll
        for (int i = 0; i < 4; i++)
            #pragma unroll
            for (int j = 0; j < 4; j++)
                #pragma unroll
                for (int q = 0; q < 4; q++) st[(i * 4 + j) * 4 + q] = acc[i][j][q];
    }

    #pragma unroll
    for (int i = 0; i < 4; i++)
        #pragma unroll
        for (int j = 0; j < 4; j++)
            #pragma unroll
            for (int q = 0; q < 4; q++) acc[i][j][q] = 0.f;
    gemm_pass<K>(arow, browU, sm, uBase, lrow, lhal, wm, wn, lane, acc);

    const int mrow = mt * BM + wm * 64;
    const int ncol = nt * BN + wn * 32;
    const float* st = stash + tid * 64;
    #pragma unroll
    for (int i = 0; i < 4; i++) {
        int r0 = mrow + i * 16 + (lane >> 2);
        #pragma unroll
        for (int j = 0; j < 4; j++) {
            int c0 = ncol + j * 8 + 2 * (lane & 3);
            float g0 = st[(i * 4 + j) * 4 + 0], g1 = st[(i * 4 + j) * 4 + 1];
            float g2 = st[(i * 4 + j) * 4 + 2], g3 = st[(i * 4 + j) * 4 + 3];
            float* p0 = g_h + (size_t)r0 * I_DIM + c0;
            p0[0] = g0 / (1.f + __expf(-g0)) * acc[i][j][0];
            p0[1] = g1 / (1.f + __expf(-g1)) * acc[i][j][1];
            float* p1 = p0 + (size_t)8 * I_DIM;
            p1[0] = g2 / (1.f + __expf(-g2)) * acc[i][j][2];
            p1[1] = g3 / (1.f + __expf(-g3)) * acc[i][j][3];
        }
    }
}

// ---------------- GEMM2: y = h @ w2s[e]^T -----------------------------------
__global__ void __launch_bounds__(256, 2) k_gemm2(const float* __restrict__ Wall) {
    constexpr int K = I_DIM;
    const int mt = blockIdx.y, nt = blockIdx.x;
    const int expert = g_tile_expert[mt];
    if (expert < 0) return;
    const float* __restrict__ Wb = Wall + (size_t)expert * H_DIM * K;

    __shared__ __align__(128) char sm[STAGE_B];

    const int tid = threadIdx.x, lane = tid & 31, wid = tid >> 5;
    const int wm = wid & 1, wn = wid >> 1;
    const int lrow = tid >> 1, lhal = tid & 1;

    const float* arow = g_h + (size_t)(mt * BM + lrow) * K;
    const float* brow = Wb + (size_t)(nt * BN + lrow) * K;

    const uint32_t uBase = smem_u32(sm);
    float acc[4][4][4];
    #pragma unroll
    for (int i = 0; i < 4; i++)
        #pragma unroll
        for (int j = 0; j < 4; j++)
            #pragma unroll
            for (int q = 0; q < 4; q++) acc[i][j][q] = 0.f;
    gemm_pass<K>(arow, brow, sm, uBase, lrow, lhal, wm, wn, lane, acc);

    const int mrow = mt * BM + wm * 64;
    const int ncol = nt * BN + wn * 32;
    #pragma unroll
    for (int i = 0; i < 4; i++) {
        int r0 = mrow + i * 16 + (lane >> 2);
        #pragma unroll
        for (int j = 0; j < 4; j++) {
            int c0 = ncol + j * 8 + 2 * (lane & 3);
            float* p0 = g_y + (size_t)r0 * H_DIM + c0;
            p0[0] = acc[i][j][0];
            p0[1] = acc[i][j][1];
            float* p1 = p0 + (size_t)8 * H_DIM;
            p1[0] = acc[i][j][2];
            p1[1] = acc[i][j][3];
        }
    }
}

// ---------------- combine ---------------------------------------------------
__global__ void k_combine(float* __restrict__ out) {
    int idx = blockIdx.x * blockDim.x + threadIdx.x;
    if (idx >= T_TOK * (H_DIM / 4)) return;
    int t = idx / (H_DIM / 4);
    int n = (idx % (H_DIM / 4)) * 4;
    int   s0 = g_tok_slot[t * 2 + 0], s1 = g_tok_slot[t * 2 + 1];
    float w0 = g_tok_w [t * 2 + 0], w1 = g_tok_w [t * 2 + 1];
    const float4 y0 = *(const float4*)&g_y[(size_t)s0 * H_DIM + n];
    const float4 y1 = *(const float4*)&g_y[(size_t)s1 * H_DIM + n];
    float4 o;
    o.x = w0 * y0.x + w1 * y1.x;
    o.y = w0 * y0.y + w1 * y1.y;
    o.z = w0 * y0.z + w1 * y1.z;
    o.w = w0 * y0.w + w1 * y1.w;
    *(float4*)&out[(size_t)t * H_DIM + n] = o;
}

// ---------------- launch ----------------------------------------------------
extern "C" void kernel_launch(void* const* d_in, const int* in_sizes, int n_in,
                              void* d_out, int out_size) {
    const float* x      = (const float*)d_in[0];
    const float* gate_w = (const float*)d_in[1];
    const float* ws     = (const float*)d_in[2];
    const float* w2s    = (const float*)d_in[3];
    float* out = (float*)d_out;

    cudaFuncSetAttribute(k_gemm1, cudaFuncAttributeMaxDynamicSharedMemorySize, DYN1);

    k_init<<<(MAX_SLOTS + 255) / 256, 256>>>();
    k_route<<<T_TOK, 512>>>(x, gate_w);
    k_offsets<<<1, 32>>>();
    k_scatter<<<(T_TOK + 255) / 256, 256>>>();

    k_gemm1<<<dim3(I_DIM / BN, M_TILES), 256, DYN1>>>(x, ws);
    k_gemm2<<<dim3(H_DIM / BN, M_TILES), 256>>>(w2s);
    k_combine<<<(T_TOK * (H_DIM / 4) + 255) / 256, 256>>>(out);
}

// round 12
// speedup vs baseline: 2.7541x; 1.3410x over previous
#include <cuda_runtime.h>
#include <cuda_fp16.h>
#include <math.h>
#include <stdint.h>

#define T_TOK 4096
#define H_DIM 2048
#define I_DIM 2048
#define E_NUM 16

#define BM 128
#define BN 128
#define KC 32
#define PITCH 80                      // bytes per smem row (32 fp16 = 64B + pad)
#define TILE_B (BM * PITCH)           // 10240
#define STAGE_B (2 * TILE_B)          // A | B = 20480
#define STASH_B (256 * 64 * 4)        // 65536
#define DYN1 (STAGE_B + STASH_B)      // 86016

#define MAX_SLOTS (T_TOK * 2 + E_NUM * BM)   // 10240
#define M_TILES   (MAX_SLOTS / BM)           // 80

// ---------------- scratch ---------------------------------------------------
__device__ int   g_slot_token[MAX_SLOTS];
__device__ int   g_tile_expert[M_TILES];
__device__ int   g_counts[E_NUM];
__device__ int   g_cursor[E_NUM];
__device__ int   g_seg_start[E_NUM];
__device__ int   g_tok_eid[T_TOK * 2];
__device__ int   g_tok_slot[T_TOK * 2];
__device__ float g_tok_w[T_TOK * 2];

__device__ float g_h[(size_t)MAX_SLOTS * I_DIM];
__device__ float g_y[(size_t)MAX_SLOTS * H_DIM];

// ---------------- helpers ---------------------------------------------------
__device__ __forceinline__ uint32_t smem_u32(const void* p) {
    uint32_t a;
    asm("{ .reg .u64 t; cvta.to.shared.u64 t, %1; cvt.u32.u64 %0, t; }" : "=r"(a) : "l"(p));
    return a;
}

#define LDSM4(R, A)                                                             \
    asm volatile("ldmatrix.sync.aligned.m8n8.x4.shared.b16 {%0,%1,%2,%3}, [%4];" \
        : "=r"((R)[0]), "=r"((R)[1]), "=r"((R)[2]), "=r"((R)[3]) : "r"(A))

__device__ __forceinline__ void mma_f16(float* d, const uint32_t* a, const uint32_t* b) {
    asm volatile("mma.sync.aligned.m16n8k16.row.col.f32.f16.f16.f32 "
        "{%0,%1,%2,%3}, {%4,%5,%6,%7}, {%8,%9}, {%0,%1,%2,%3};"
        : "+f"(d[0]), "+f"(d[1]), "+f"(d[2]), "+f"(d[3])
        : "r"(a[0]), "r"(a[1]), "r"(a[2]), "r"(a[3]), "r"(b[0]), "r"(b[1]));
}

// fp32x4 -> fp16x4 (8B) pitched smem store
__device__ __forceinline__ void cvt_store(char* t, int row, int colf, float4 v) {
    __half2 h01 = __floats2half2_rn(v.x, v.y);
    __half2 h23 = __floats2half2_rn(v.z, v.w);
    uint32_t off = (uint32_t)(row * PITCH + colf * 2);
    *(uint2*)(t + off) = make_uint2(*reinterpret_cast<uint32_t*>(&h01),
                                    *reinterpret_cast<uint32_t*>(&h23));
}

// ---------------- routing / bookkeeping -------------------------------------
__global__ void k_init() {
    int i = blockIdx.x * blockDim.x + threadIdx.x;
    if (i < MAX_SLOTS) g_slot_token[i] = -1;
    if (i < E_NUM) { g_counts[i] = 0; g_cursor[i] = 0; }
}

__global__ void __launch_bounds__(512) k_route(const float* __restrict__ x,
                                               const float* __restrict__ gw) {
    int t = blockIdx.x, warp = threadIdx.x >> 5, lane = threadIdx.x & 31;
    const float* xr = x + (size_t)t * H_DIM;
    const float* gr = gw + (size_t)warp * H_DIM;
    float s = 0.f;
    for (int k = lane; k < H_DIM; k += 32) s += xr[k] * gr[k];
    #pragma unroll
    for (int o = 16; o; o >>= 1) s += __shfl_xor_sync(0xffffffffu, s, o);
    __shared__ float logits[E_NUM];
    if (lane == 0) logits[warp] = s;
    __syncthreads();
    if (threadIdx.x == 0) {
        int i0 = -1, i1 = -1; float v0 = -1e30f, v1 = -1e30f;
        #pragma unroll
        for (int e = 0; e < E_NUM; e++) {
            float v = logits[e];
            if (v > v0) { v1 = v0; i1 = i0; v0 = v; i0 = e; }
            else if (v > v1) { v1 = v; i1 = e; }
        }
        float e1 = expf(v1 - v0);
        float w0 = 1.f / (1.f + e1);
        g_tok_eid[t * 2 + 0] = i0;  g_tok_eid[t * 2 + 1] = i1;
        g_tok_w [t * 2 + 0] = w0;  g_tok_w [t * 2 + 1] = e1 * w0;
        atomicAdd(&g_counts[i0], 1);
        atomicAdd(&g_counts[i1], 1);
    }
}

__global__ void k_offsets() {
    if (threadIdx.x == 0 && blockIdx.x == 0) {
        int run = 0;
        for (int e = 0; e < E_NUM; e++) {
            g_seg_start[e] = run;
            int padded = (g_counts[e] + BM - 1) / BM * BM;
            for (int tt = run / BM; tt < (run + padded) / BM; tt++) g_tile_expert[tt] = e;
            run += padded;
        }
        for (int tt = run / BM; tt < M_TILES; tt++) g_tile_expert[tt] = -1;
    }
}

__global__ void k_scatter() {
    int t = blockIdx.x * blockDim.x + threadIdx.x;
    if (t >= T_TOK) return;
    #pragma unroll
    for (int k = 0; k < 2; k++) {
        int e = g_tok_eid[t * 2 + k];
        int pos = atomicAdd(&g_cursor[e], 1);
        int slot = g_seg_start[e] + pos;
        g_slot_token[slot] = t;
        g_tok_slot[t * 2 + k] = slot;
    }
}

// ---------------- fp16 single-term mainloop, register-prefetched ------------
template <int K>
__device__ __forceinline__ void gemm_pass(const float* arow, const float* brow,
                                          char* sm, uint32_t uBase,
                                          int lrow, int lhal, int wm, int wn, int lane,
                                          float acc[4][4][4]) {
    constexpr int NCH = K / KC;
    float4 pa[4], pb[4];
    #pragma unroll
    for (int i = 0; i < 4; i++) {
        pa[i] = arow ? *(const float4*)(arow + lhal * 16 + i * 4)
                     : make_float4(0.f, 0.f, 0.f, 0.f);
        pb[i] = *(const float4*)(brow + lhal * 16 + i * 4);
    }
    #pragma unroll
    for (int i = 0; i < 4; i++) {
        cvt_store(sm,          lrow, lhal * 16 + i * 4, pa[i]);
        cvt_store(sm + TILE_B, lrow, lhal * 16 + i * 4, pb[i]);
    }
    __syncthreads();

    for (int ic = 0; ic < NCH; ic++) {
        if (ic + 1 < NCH) {
            const int kb = (ic + 1) * KC;
            #pragma unroll
            for (int i = 0; i < 4; i++) {
                pa[i] = arow ? *(const float4*)(arow + kb + lhal * 16 + i * 4)
                             : make_float4(0.f, 0.f, 0.f, 0.f);
                pb[i] = *(const float4*)(brow + kb + lhal * 16 + i * 4);
            }
        }
        #pragma unroll
        for (int k16 = 0; k16 < 2; k16++) {
            uint32_t af[4][4];
            #pragma unroll
            for (int i = 0; i < 4; i++) {
                uint32_t ad = uBase + (uint32_t)((wm * 64 + i * 16 + (lane & 15)) * PITCH
                                                 + k16 * 32 + (lane >> 4) * 16);
                LDSM4(af[i], ad);
            }
            uint32_t bf[8];
            #pragma unroll
            for (int p = 0; p < 2; p++) {
                uint32_t bd = uBase + (uint32_t)TILE_B
                            + (uint32_t)((wn * 32 + p * 16 + (lane & 7) + ((lane >> 4) << 3)) * PITCH
                                         + k16 * 32 + ((lane >> 3) & 1) * 16);
                LDSM4(&bf[p * 4], bd);
            }
            #pragma unroll
            for (int i = 0; i < 4; i++)
                #pragma unroll
                for (int j = 0; j < 4; j++)
                    mma_f16(acc[i][j], af[i], &bf[(j >> 1) * 4 + (j & 1) * 2]);
        }
        __syncthreads();
        if (ic + 1 < NCH) {
            #pragma unroll
            for (int i = 0; i < 4; i++) {
                cvt_store(sm,          lrow, lhal * 16 + i * 4, pa[i]);
                cvt_store(sm + TILE_B, lrow, lhal * 16 + i * 4, pb[i]);
            }
            __syncthreads();
        }
    }
}

// ---------------- GEMM1 fused: h = silu(x@Wg^T) * (x@Wu^T) ------------------
__global__ void __launch_bounds__(256, 1) k_gemm1(const float* __restrict__ X,
                                                  const float* __restrict__ Wall) {
    constexpr int K = H_DIM;
    const int mt = blockIdx.y, nt = blockIdx.x;
    const int expert = g_tile_expert[mt];
    if (expert < 0) return;
    const float* __restrict__ Wb = Wall + (size_t)expert * (2 * I_DIM) * K;

    extern __shared__ __align__(128) char sm[];
    float* stash = (float*)(sm + STAGE_B);

    const int tid = threadIdx.x, lane = tid & 31, wid = tid >> 5;
    const int wm = wid & 1, wn = wid >> 1;
    const int lrow = tid >> 1, lhal = tid & 1;

    int tok = g_slot_token[mt * BM + lrow];
    const float* arow = (tok >= 0) ? (X + (size_t)tok * K) : (const float*)0;
    const float* browG = Wb + (size_t)(nt * BN + lrow) * K;
    const float* browU = Wb + (size_t)(I_DIM + nt * BN + lrow) * K;

    const uint32_t uBase = smem_u32(sm);
    float acc[4][4][4];

    #pragma unroll
    for (int i = 0; i < 4; i++)
        #pragma unroll
        for (int j = 0; j < 4; j++)
            #pragma unroll
            for (int q = 0; q < 4; q++) acc[i][j][q] = 0.f;
    gemm_pass<K>(arow, browG, sm, uBase, lrow, lhal, wm, wn, lane, acc);
    {
        float* st = stash + tid * 64;
        #pragma unroll
        for (int i = 0; i < 4; i++)
            #pragma unroll
            for (int j = 0; j < 4; j++)
                #pragma unroll
                for (int q = 0; q < 4; q++) st[(i * 4 + j) * 4 + q] = acc[i][j][q];
    }

    #pragma unroll
    for (int i = 0; i < 4; i++)
        #pragma unroll
        for (int j = 0; j < 4; j++)
            #pragma unroll
            for (int q = 0; q < 4; q++) acc[i][j][q] = 0.f;
    gemm_pass<K>(arow, browU, sm, uBase, lrow, lhal, wm, wn, lane, acc);

    const int mrow = mt * BM + wm * 64;
    const int ncol = nt * BN + wn * 32;
    const float* st = stash + tid * 64;
    #pragma unroll
    for (int i = 0; i < 4; i++) {
        int r0 = mrow + i * 16 + (lane >> 2);
        #pragma unroll
        for (int j = 0; j < 4; j++) {
            int c0 = ncol + j * 8 + 2 * (lane & 3);
            float g0 = st[(i * 4 + j) * 4 + 0], g1 = st[(i * 4 + j) * 4 + 1];
            float g2 = st[(i * 4 + j) * 4 + 2], g3 = st[(i * 4 + j) * 4 + 3];
            float* p0 = g_h + (size_t)r0 * I_DIM + c0;
            p0[0] = g0 / (1.f + __expf(-g0)) * acc[i][j][0];
            p0[1] = g1 / (1.f + __expf(-g1)) * acc[i][j][1];
            float* p1 = p0 + (size_t)8 * I_DIM;
            p1[0] = g2 / (1.f + __expf(-g2)) * acc[i][j][2];
            p1[1] = g3 / (1.f + __expf(-g3)) * acc[i][j][3];
        }
    }
}

// ---------------- GEMM2: y = h @ w2s[e]^T -----------------------------------
__global__ void __launch_bounds__(256, 1) k_gemm2(const float* __restrict__ Wall) {
    constexpr int K = I_DIM;
    const int mt = blockIdx.y, nt = blockIdx.x;
    const int expert = g_tile_expert[mt];
    if (expert < 0) return;
    const float* __restrict__ Wb = Wall + (size_t)expert * H_DIM * K;

    __shared__ __align__(128) char sm[STAGE_B];

    const int tid = threadIdx.x, lane = tid & 31, wid = tid >> 5;
    const int wm = wid & 1, wn = wid >> 1;
    const int lrow = tid >> 1, lhal = tid & 1;

    const float* arow = g_h + (size_t)(mt * BM + lrow) * K;
    const float* brow = Wb + (size_t)(nt * BN + lrow) * K;

    const uint32_t uBase = smem_u32(sm);
    float acc[4][4][4];
    #pragma unroll
    for (int i = 0; i < 4; i++)
        #pragma unroll
        for (int j = 0; j < 4; j++)
            #pragma unroll
            for (int q = 0; q < 4; q++) acc[i][j][q] = 0.f;
    gemm_pass<K>(arow, brow, sm, uBase, lrow, lhal, wm, wn, lane, acc);

    const int mrow = mt * BM + wm * 64;
    const int ncol = nt * BN + wn * 32;
    #pragma unroll
    for (int i = 0; i < 4; i++) {
        int r0 = mrow + i * 16 + (lane >> 2);
        #pragma unroll
        for (int j = 0; j < 4; j++) {
            int c0 = ncol + j * 8 + 2 * (lane & 3);
            float* p0 = g_y + (size_t)r0 * H_DIM + c0;
            p0[0] = acc[i][j][0];
            p0[1] = acc[i][j][1];
            float* p1 = p0 + (size_t)8 * H_DIM;
            p1[0] = acc[i][j][2];
            p1[1] = acc[i][j][3];
        }
    }
}

// ---------------- combine ---------------------------------------------------
__global__ void k_combine(float* __restrict__ out) {
    int idx = blockIdx.x * blockDim.x + threadIdx.x;
    if (idx >= T_TOK * (H_DIM / 4)) return;
    int t = idx / (H_DIM / 4);
    int n = (idx % (H_DIM / 4)) * 4;
    int   s0 = g_tok_slot[t * 2 + 0], s1 = g_tok_slot[t * 2 + 1];
    float w0 = g_tok_w [t * 2 + 0], w1 = g_tok_w [t * 2 + 1];
    const float4 y0 = *(const float4*)&g_y[(size_t)s0 * H_DIM + n];
    const float4 y1 = *(const float4*)&g_y[(size_t)s1 * H_DIM + n];
    float4 o;
    o.x = w0 * y0.x + w1 * y1.x;
    o.y = w0 * y0.y + w1 * y1.y;
    o.z = w0 * y0.z + w1 * y1.z;
    o.w = w0 * y0.w + w1 * y1.w;
    *(float4*)&out[(size_t)t * H_DIM + n] = o;
}

// ---------------- launch ----------------------------------------------------
extern "C" void kernel_launch(void* const* d_in, const int* in_sizes, int n_in,
                              void* d_out, int out_size) {
    const float* x      = (const float*)d_in[0];
    const float* gate_w = (const float*)d_in[1];
    const float* ws     = (const float*)d_in[2];
    const float* w2s    = (const float*)d_in[3];
    float* out = (float*)d_out;

    cudaFuncSetAttribute(k_gemm1, cudaFuncAttributeMaxDynamicSharedMemorySize, DYN1);

    k_init<<<(MAX_SLOTS + 255) / 256, 256>>>();
    k_route<<<T_TOK, 512>>>(x, gate_w);
    k_offsets<<<1, 32>>>();
    k_scatter<<<(T_TOK + 255) / 256, 256>>>();

    k_gemm1<<<dim3(I_DIM / BN, M_TILES), 256, DYN1>>>(x, ws);
    k_gemm2<<<dim3(H_DIM / BN, M_TILES), 256>>>(w2s);
    k_combine<<<(T_TOK * (H_DIM / 4) + 255) / 256, 256>>>(out);
}

// round 13
// speedup vs baseline: 2.9063x; 1.0552x over previous
#include <cuda_runtime.h>
#include <cuda_fp16.h>
#include <math.h>
#include <stdint.h>

#define T_TOK 4096
#define H_DIM 2048
#define I_DIM 2048
#define E_NUM 16

#define BM 128
#define BN 128
#define KC 32
#define PITCH 80                      // bytes per smem row (32 fp16 = 64B + pad)
#define TILE_B (BM * PITCH)           // 10240
#define STAGE_B (2 * TILE_B)          // A | B = 20480
#define STASH_B (256 * 64 * 4)        // 65536
#define DYN1 (2 * STAGE_B + STASH_B)  // 106496
#define DYN2 (2 * STAGE_B)            // 40960

#define MAX_SLOTS (T_TOK * 2 + E_NUM * BM)   // 10240
#define M_TILES   (MAX_SLOTS / BM)           // 80

// ---------------- scratch ---------------------------------------------------
__device__ int   g_slot_token[MAX_SLOTS];
__device__ int   g_tile_expert[M_TILES];
__device__ int   g_counts[E_NUM];
__device__ int   g_cursor[E_NUM];
__device__ int   g_seg_start[E_NUM];
__device__ int   g_tok_eid[T_TOK * 2];
__device__ int   g_tok_slot[T_TOK * 2];
__device__ float g_tok_w[T_TOK * 2];

__device__ float g_h[(size_t)MAX_SLOTS * I_DIM];
__device__ float g_y[(size_t)MAX_SLOTS * H_DIM];

// ---------------- helpers ---------------------------------------------------
__device__ __forceinline__ uint32_t smem_u32(const void* p) {
    uint32_t a;
    asm("{ .reg .u64 t; cvta.to.shared.u64 t, %1; cvt.u32.u64 %0, t; }" : "=r"(a) : "l"(p));
    return a;
}

#define LDSM4(R, A)                                                             \
    asm volatile("ldmatrix.sync.aligned.m8n8.x4.shared.b16 {%0,%1,%2,%3}, [%4];" \
        : "=r"((R)[0]), "=r"((R)[1]), "=r"((R)[2]), "=r"((R)[3]) : "r"(A))

__device__ __forceinline__ void mma_f16(float* d, const uint32_t* a, const uint32_t* b) {
    asm volatile("mma.sync.aligned.m16n8k16.row.col.f32.f16.f16.f32 "
        "{%0,%1,%2,%3}, {%4,%5,%6,%7}, {%8,%9}, {%0,%1,%2,%3};"
        : "+f"(d[0]), "+f"(d[1]), "+f"(d[2]), "+f"(d[3])
        : "r"(a[0]), "r"(a[1]), "r"(a[2]), "r"(a[3]), "r"(b[0]), "r"(b[1]));
}

__device__ __forceinline__ void cvt_store(char* t, int row, int colf, float4 v) {
    __half2 h01 = __floats2half2_rn(v.x, v.y);
    __half2 h23 = __floats2half2_rn(v.z, v.w);
    uint32_t off = (uint32_t)(row * PITCH + colf * 2);
    *(uint2*)(t + off) = make_uint2(*reinterpret_cast<uint32_t*>(&h01),
                                    *reinterpret_cast<uint32_t*>(&h23));
}

// ---------------- routing / bookkeeping -------------------------------------
__global__ void k_init() {
    int i = blockIdx.x * blockDim.x + threadIdx.x;
    if (i < MAX_SLOTS) g_slot_token[i] = -1;
    if (i < E_NUM) { g_counts[i] = 0; g_cursor[i] = 0; }
}

__global__ void __launch_bounds__(512) k_route(const float* __restrict__ x,
                                               const float* __restrict__ gw) {
    int t = blockIdx.x, warp = threadIdx.x >> 5, lane = threadIdx.x & 31;
    const float* xr = x + (size_t)t * H_DIM;
    const float* gr = gw + (size_t)warp * H_DIM;
    float s = 0.f;
    for (int k = lane; k < H_DIM; k += 32) s += xr[k] * gr[k];
    #pragma unroll
    for (int o = 16; o; o >>= 1) s += __shfl_xor_sync(0xffffffffu, s, o);
    __shared__ float logits[E_NUM];
    if (lane == 0) logits[warp] = s;
    __syncthreads();
    if (threadIdx.x == 0) {
        int i0 = -1, i1 = -1; float v0 = -1e30f, v1 = -1e30f;
        #pragma unroll
        for (int e = 0; e < E_NUM; e++) {
            float v = logits[e];
            if (v > v0) { v1 = v0; i1 = i0; v0 = v; i0 = e; }
            else if (v > v1) { v1 = v; i1 = e; }
        }
        float e1 = expf(v1 - v0);
        float w0 = 1.f / (1.f + e1);
        g_tok_eid[t * 2 + 0] = i0;  g_tok_eid[t * 2 + 1] = i1;
        g_tok_w [t * 2 + 0] = w0;  g_tok_w [t * 2 + 1] = e1 * w0;
        atomicAdd(&g_counts[i0], 1);
        atomicAdd(&g_counts[i1], 1);
    }
}

__global__ void k_offsets() {
    if (threadIdx.x == 0 && blockIdx.x == 0) {
        int run = 0;
        for (int e = 0; e < E_NUM; e++) {
            g_seg_start[e] = run;
            int padded = (g_counts[e] + BM - 1) / BM * BM;
            for (int tt = run / BM; tt < (run + padded) / BM; tt++) g_tile_expert[tt] = e;
            run += padded;
        }
        for (int tt = run / BM; tt < M_TILES; tt++) g_tile_expert[tt] = -1;
    }
}

__global__ void k_scatter() {
    int t = blockIdx.x * blockDim.x + threadIdx.x;
    if (t >= T_TOK) return;
    #pragma unroll
    for (int k = 0; k < 2; k++) {
        int e = g_tok_eid[t * 2 + k];
        int pos = atomicAdd(&g_cursor[e], 1);
        int slot = g_seg_start[e] + pos;
        g_slot_token[slot] = t;
        g_tok_slot[t * 2 + k] = slot;
    }
}

// ---------------- fp16 double-buffered mainloop -----------------------------
template <int K>
__device__ __forceinline__ void gemm_pass(const float* arow, const float* brow,
                                          char* sm, uint32_t uBase,
                                          int lrow, int lhal, int wm, int wn, int lane,
                                          float acc[4][4][4]) {
    constexpr int NCH = K / KC;
    float4 pa[4], pb[4];
    // prologue: chunk 0 -> buffer 0
    #pragma unroll
    for (int i = 0; i < 4; i++) {
        pa[i] = arow ? *(const float4*)(arow + lhal * 16 + i * 4)
                     : make_float4(0.f, 0.f, 0.f, 0.f);
        pb[i] = *(const float4*)(brow + lhal * 16 + i * 4);
    }
    #pragma unroll
    for (int i = 0; i < 4; i++) {
        cvt_store(sm,          lrow, lhal * 16 + i * 4, pa[i]);
        cvt_store(sm + TILE_B, lrow, lhal * 16 + i * 4, pb[i]);
    }
    __syncthreads();

    for (int ic = 0; ic < NCH; ic++) {
        const uint32_t cur = uBase + (uint32_t)((ic & 1) * STAGE_B);
        char* nxt = sm + ((ic + 1) & 1) * STAGE_B;

        // global loads for next chunk, in flight under the MMAs
        if (ic + 1 < NCH) {
            const int kb = (ic + 1) * KC;
            #pragma unroll
            for (int i = 0; i < 4; i++) {
                pa[i] = arow ? *(const float4*)(arow + kb + lhal * 16 + i * 4)
                             : make_float4(0.f, 0.f, 0.f, 0.f);
                pb[i] = *(const float4*)(brow + kb + lhal * 16 + i * 4);
            }
        }

        #pragma unroll
        for (int k16 = 0; k16 < 2; k16++) {
            uint32_t af[4][4];
            #pragma unroll
            for (int i = 0; i < 4; i++) {
                uint32_t ad = cur + (uint32_t)((wm * 64 + i * 16 + (lane & 15)) * PITCH
                                               + k16 * 32 + (lane >> 4) * 16);
                LDSM4(af[i], ad);
            }
            uint32_t bf[8];
            #pragma unroll
            for (int p = 0; p < 2; p++) {
                uint32_t bd = cur + (uint32_t)TILE_B
                            + (uint32_t)((wn * 32 + p * 16 + (lane & 7) + ((lane >> 4) << 3)) * PITCH
                                         + k16 * 32 + ((lane >> 3) & 1) * 16);
                LDSM4(&bf[p * 4], bd);
            }
            #pragma unroll
            for (int i = 0; i < 4; i++)
                #pragma unroll
                for (int j = 0; j < 4; j++)
                    mma_f16(acc[i][j], af[i], &bf[(j >> 1) * 4 + (j & 1) * 2]);
        }

        // stage next chunk into the other buffer; ONE barrier per chunk
        if (ic + 1 < NCH) {
            #pragma unroll
            for (int i = 0; i < 4; i++) {
                cvt_store(nxt,          lrow, lhal * 16 + i * 4, pa[i]);
                cvt_store(nxt + TILE_B, lrow, lhal * 16 + i * 4, pb[i]);
            }
            __syncthreads();
        }
    }
    __syncthreads();   // buffers reusable by the caller's next pass
}

// ---------------- GEMM1 fused: h = silu(x@Wg^T) * (x@Wu^T) ------------------
__global__ void __launch_bounds__(256, 1) k_gemm1(const float* __restrict__ X,
                                                  const float* __restrict__ Wall) {
    constexpr int K = H_DIM;
    const int mt = blockIdx.y, nt = blockIdx.x;
    const int expert = g_tile_expert[mt];
    if (expert < 0) return;
    const float* __restrict__ Wb = Wall + (size_t)expert * (2 * I_DIM) * K;

    extern __shared__ __align__(128) char sm[];
    float* stash = (float*)(sm + 2 * STAGE_B);

    const int tid = threadIdx.x, lane = tid & 31, wid = tid >> 5;
    const int wm = wid & 1, wn = wid >> 1;
    const int lrow = tid >> 1, lhal = tid & 1;

    int tok = g_slot_token[mt * BM + lrow];
    const float* arow = (tok >= 0) ? (X + (size_t)tok * K) : (const float*)0;
    const float* browG = Wb + (size_t)(nt * BN + lrow) * K;
    const float* browU = Wb + (size_t)(I_DIM + nt * BN + lrow) * K;

    const uint32_t uBase = smem_u32(sm);
    float acc[4][4][4];

    #pragma unroll
    for (int i = 0; i < 4; i++)
        #pragma unroll
        for (int j = 0; j < 4; j++)
            #pragma unroll
            for (int q = 0; q < 4; q++) acc[i][j][q] = 0.f;
    gemm_pass<K>(arow, browG, sm, uBase, lrow, lhal, wm, wn, lane, acc);
    {
        float* st = stash + tid * 64;
        #pragma unroll
        for (int i = 0; i < 4; i++)
            #pragma unroll
            for (int j = 0; j < 4; j++)
                #pragma unroll
                for (int q = 0; q < 4; q++) st[(i * 4 + j) * 4 + q] = acc[i][j][q];
    }

    #pragma unroll
    for (int i = 0; i < 4; i++)
        #pragma unroll
        for (int j = 0; j < 4; j++)
            #pragma unroll
            for (int q = 0; q < 4; q++) acc[i][j][q] = 0.f;
    gemm_pass<K>(arow, browU, sm, uBase, lrow, lhal, wm, wn, lane, acc);

    const int mrow = mt * BM + wm * 64;
    const int ncol = nt * BN + wn * 32;
    const float* st = stash + tid * 64;
    #pragma unroll
    for (int i = 0; i < 4; i++) {
        int r0 = mrow + i * 16 + (lane >> 2);
        #pragma unroll
        for (int j = 0; j < 4; j++) {
            int c0 = ncol + j * 8 + 2 * (lane & 3);
            float g0 = st[(i * 4 + j) * 4 + 0], g1 = st[(i * 4 + j) * 4 + 1];
            float g2 = st[(i * 4 + j) * 4 + 2], g3 = st[(i * 4 + j) * 4 + 3];
            float* p0 = g_h + (size_t)r0 * I_DIM + c0;
            p0[0] = g0 / (1.f + __expf(-g0)) * acc[i][j][0];
            p0[1] = g1 / (1.f + __expf(-g1)) * acc[i][j][1];
            float* p1 = p0 + (size_t)8 * I_DIM;
            p1[0] = g2 / (1.f + __expf(-g2)) * acc[i][j][2];
            p1[1] = g3 / (1.f + __expf(-g3)) * acc[i][j][3];
        }
    }
}

// ---------------- GEMM2: y = h @ w2s[e]^T -----------------------------------
__global__ void __launch_bounds__(256, 1) k_gemm2(const float* __restrict__ Wall) {
    constexpr int K = I_DIM;
    const int mt = blockIdx.y, nt = blockIdx.x;
    const int expert = g_tile_expert[mt];
    if (expert < 0) return;
    const float* __restrict__ Wb = Wall + (size_t)expert * H_DIM * K;

    extern __shared__ __align__(128) char sm[];

    const int tid = threadIdx.x, lane = tid & 31, wid = tid >> 5;
    const int wm = wid & 1, wn = wid >> 1;
    const int lrow = tid >> 1, lhal = tid & 1;

    const float* arow = g_h + (size_t)(mt * BM + lrow) * K;
    const float* brow = Wb + (size_t)(nt * BN + lrow) * K;

    const uint32_t uBase = smem_u32(sm);
    float acc[4][4][4];
    #pragma unroll
    for (int i = 0; i < 4; i++)
        #pragma unroll
        for (int j = 0; j < 4; j++)
            #pragma unroll
            for (int q = 0; q < 4; q++) acc[i][j][q] = 0.f;
    gemm_pass<K>(arow, brow, sm, uBase, lrow, lhal, wm, wn, lane, acc);

    const int mrow = mt * BM + wm * 64;
    const int ncol = nt * BN + wn * 32;
    #pragma unroll
    for (int i = 0; i < 4; i++) {
        int r0 = mrow + i * 16 + (lane >> 2);
        #pragma unroll
        for (int j = 0; j < 4; j++) {
            int c0 = ncol + j * 8 + 2 * (lane & 3);
            float* p0 = g_y + (size_t)r0 * H_DIM + c0;
            p0[0] = acc[i][j][0];
            p0[1] = acc[i][j][1];
            float* p1 = p0 + (size_t)8 * H_DIM;
            p1[0] = acc[i][j][2];
            p1[1] = acc[i][j][3];
        }
    }
}

// ---------------- combine ---------------------------------------------------
__global__ void k_combine(float* __restrict__ out) {
    int idx = blockIdx.x * blockDim.x + threadIdx.x;
    if (idx >= T_TOK * (H_DIM / 4)) return;
    int t = idx / (H_DIM / 4);
    int n = (idx % (H_DIM / 4)) * 4;
    int   s0 = g_tok_slot[t * 2 + 0], s1 = g_tok_slot[t * 2 + 1];
    float w0 = g_tok_w [t * 2 + 0], w1 = g_tok_w [t * 2 + 1];
    const float4 y0 = *(const float4*)&g_y[(size_t)s0 * H_DIM + n];
    const float4 y1 = *(const float4*)&g_y[(size_t)s1 * H_DIM + n];
    float4 o;
    o.x = w0 * y0.x + w1 * y1.x;
    o.y = w0 * y0.y + w1 * y1.y;
    o.z = w0 * y0.z + w1 * y1.z;
    o.w = w0 * y0.w + w1 * y1.w;
    *(float4*)&out[(size_t)t * H_DIM + n] = o;
}

// ---------------- launch ----------------------------------------------------
extern "C" void kernel_launch(void* const* d_in, const int* in_sizes, int n_in,
                              void* d_out, int out_size) {
    const float* x      = (const float*)d_in[0];
    const float* gate_w = (const float*)d_in[1];
    const float* ws     = (const float*)d_in[2];
    const float* w2s    = (const float*)d_in[3];
    float* out = (float*)d_out;

    cudaFuncSetAttribute(k_gemm1, cudaFuncAttributeMaxDynamicSharedMemorySize, DYN1);
    cudaFuncSetAttribute(k_gemm2, cudaFuncAttributeMaxDynamicSharedMemorySize, DYN2);

    k_init<<<(MAX_SLOTS + 255) / 256, 256>>>();
    k_route<<<T_TOK, 512>>>(x, gate_w);
    k_offsets<<<1, 32>>>();
    k_scatter<<<(T_TOK + 255) / 256, 256>>>();

    k_gemm1<<<dim3(I_DIM / BN, M_TILES), 256, DYN1>>>(x, ws);
    k_gemm2<<<dim3(H_DIM / BN, M_TILES), 256, DYN2>>>(w2s);
    k_combine<<<(T_TOK * (H_DIM / 4) + 255) / 256, 256>>>(out);
}

// round 16
// speedup vs baseline: 3.6984x; 1.2726x over previous
#include <cuda_runtime.h>
#include <cuda_fp16.h>
#include <math.h>
#include <stdint.h>

#define T_TOK 4096
#define H_DIM 2048
#define I_DIM 2048
#define E_NUM 16

#define BM 128
#define BN 128
#define KC 32
#define PITCH 80                      // bytes per smem row (32 fp16 = 64B + pad)
#define TILE_B (BM * PITCH)           // 10240
#define STAGE_B (2 * TILE_B)          // A | B = 20480
#define STASH_B (256 * 64 * 4)        // 65536
#define DYN1 (2 * STAGE_B + STASH_B)  // 106496
#define DYN2 (2 * STAGE_B)            // 40960

#define MAX_SLOTS (T_TOK * 2 + E_NUM * BM)   // 10240
#define M_TILES   (MAX_SLOTS / BM)           // 80

// ---------------- scratch ---------------------------------------------------
__device__ int   g_slot_token[MAX_SLOTS];
__device__ int   g_tile_expert[M_TILES];
__device__ int   g_counts[E_NUM];
__device__ int   g_cursor[E_NUM];
__device__ int   g_seg_start[E_NUM];
__device__ int   g_tok_eid[T_TOK * 2];
__device__ int   g_tok_slot[T_TOK * 2];
__device__ float g_tok_w[T_TOK * 2];

__device__ __half g_xh[(size_t)T_TOK * H_DIM];                 // x in fp16
__device__ __half g_w1h[(size_t)E_NUM * 2 * I_DIM * H_DIM];    // ws in fp16
__device__ __half g_w2h[(size_t)E_NUM * H_DIM * I_DIM];        // w2s in fp16
__device__ __half g_h[(size_t)MAX_SLOTS * I_DIM];              // silu(g)*u, fp16
__device__ float  g_y[(size_t)MAX_SLOTS * H_DIM];

// ---------------- helpers ---------------------------------------------------
__device__ __forceinline__ uint32_t smem_u32(const void* p) {
    uint32_t a;
    asm("{ .reg .u64 t; cvta.to.shared.u64 t, %1; cvt.u32.u64 %0, t; }" : "=r"(a) : "l"(p));
    return a;
}

#define LDSM4(R, A)                                                             \
    asm volatile("ldmatrix.sync.aligned.m8n8.x4.shared.b16 {%0,%1,%2,%3}, [%4];" \
        : "=r"((R)[0]), "=r"((R)[1]), "=r"((R)[2]), "=r"((R)[3]) : "r"(A))

__device__ __forceinline__ void mma_f16(float* d, const uint32_t* a, const uint32_t* b) {
    asm volatile("mma.sync.aligned.m16n8k16.row.col.f32.f16.f16.f32 "
        "{%0,%1,%2,%3}, {%4,%5,%6,%7}, {%8,%9}, {%0,%1,%2,%3};"
        : "+f"(d[0]), "+f"(d[1]), "+f"(d[2]), "+f"(d[3])
        : "r"(a[0]), "r"(a[1]), "r"(a[2]), "r"(a[3]), "r"(b[0]), "r"(b[1]));
}

// ---------------- fp32 -> fp16 bulk convert ---------------------------------
// mode: 0 = x -> g_xh, 1 = ws -> g_w1h, 2 = w2s -> g_w2h
__global__ void __launch_bounds__(256) k_cvt(const float* __restrict__ src, int mode, int n8) {
    int i = blockIdx.x * blockDim.x + threadIdx.x;
    if (i >= n8) return;
    __half* dst = (mode == 0) ? g_xh : (mode == 1) ? g_w1h : g_w2h;
    const float4* s4 = (const float4*)src;
    float4 a = s4[(size_t)i * 2], b = s4[(size_t)i * 2 + 1];
    __half2 h0 = __floats2half2_rn(a.x, a.y);
    __half2 h1 = __floats2half2_rn(a.z, a.w);
    __half2 h2 = __floats2half2_rn(b.x, b.y);
    __half2 h3 = __floats2half2_rn(b.z, b.w);
    uint4 o;
    o.x = *reinterpret_cast<uint32_t*>(&h0);
    o.y = *reinterpret_cast<uint32_t*>(&h1);
    o.z = *reinterpret_cast<uint32_t*>(&h2);
    o.w = *reinterpret_cast<uint32_t*>(&h3);
    *(uint4*)(dst + (size_t)i * 8) = o;
}

// ---------------- routing / bookkeeping -------------------------------------
__global__ void k_init() {
    int i = blockIdx.x * blockDim.x + threadIdx.x;
    if (i < MAX_SLOTS) g_slot_token[i] = -1;
    if (i < E_NUM) { g_counts[i] = 0; g_cursor[i] = 0; }
}

__global__ void __launch_bounds__(512) k_route(const float* __restrict__ x,
                                               const float* __restrict__ gw) {
    int t = blockIdx.x, warp = threadIdx.x >> 5, lane = threadIdx.x & 31;
    const float* xr = x + (size_t)t * H_DIM;
    const float* gr = gw + (size_t)warp * H_DIM;
    float s = 0.f;
    for (int k = lane; k < H_DIM; k += 32) s += xr[k] * gr[k];
    #pragma unroll
    for (int o = 16; o; o >>= 1) s += __shfl_xor_sync(0xffffffffu, s, o);
    __shared__ float logits[E_NUM];
    if (lane == 0) logits[warp] = s;
    __syncthreads();
    if (threadIdx.x == 0) {
        int i0 = -1, i1 = -1; float v0 = -1e30f, v1 = -1e30f;
        #pragma unroll
        for (int e = 0; e < E_NUM; e++) {
            float v = logits[e];
            if (v > v0) { v1 = v0; i1 = i0; v0 = v; i0 = e; }
            else if (v > v1) { v1 = v; i1 = e; }
        }
        float e1 = expf(v1 - v0);
        float w0 = 1.f / (1.f + e1);
        g_tok_eid[t * 2 + 0] = i0;  g_tok_eid[t * 2 + 1] = i1;
        g_tok_w [t * 2 + 0] = w0;  g_tok_w [t * 2 + 1] = e1 * w0;
        atomicAdd(&g_counts[i0], 1);
        atomicAdd(&g_counts[i1], 1);
    }
}

__global__ void k_offsets() {
    if (threadIdx.x == 0 && blockIdx.x == 0) {
        int run = 0;
        for (int e = 0; e < E_NUM; e++) {
            g_seg_start[e] = run;
            int padded = (g_counts[e] + BM - 1) / BM * BM;
            for (int tt = run / BM; tt < (run + padded) / BM; tt++) g_tile_expert[tt] = e;
            run += padded;
        }
        for (int tt = run / BM; tt < M_TILES; tt++) g_tile_expert[tt] = -1;
    }
}

__global__ void k_scatter() {
    int t = blockIdx.x * blockDim.x + threadIdx.x;
    if (t >= T_TOK) return;
    #pragma unroll
    for (int k = 0; k < 2; k++) {
        int e = g_tok_eid[t * 2 + k];
        int pos = atomicAdd(&g_cursor[e], 1);
        int slot = g_seg_start[e] + pos;
        g_slot_token[slot] = t;
        g_tok_slot[t * 2 + k] = slot;
    }
}

// ---------------- fp16 double-buffered mainloop (STS producer, R13 proven) --
template <int K>
__device__ __forceinline__ void gemm_pass(const __half* arow, const __half* brow,
                                          char* sm, uint32_t uBase,
                                          int lrow, int lhal, int wm, int wn, int lane,
                                          float acc[4][4][4]) {
    constexpr int NCH = K / KC;
    const uint32_t so = (uint32_t)(lrow * PITCH + lhal * 32);

    uint4 va0, va1, vb0, vb1;
    // prologue: chunk 0 -> buffer 0
    {
        const char* as = (const char*)arow + lhal * 32;
        const char* bs = (const char*)brow + lhal * 32;
        va0 = *(const uint4*)as;  va1 = *(const uint4*)(as + 16);
        vb0 = *(const uint4*)bs;  vb1 = *(const uint4*)(bs + 16);
        *(uint4*)(sm + so)               = va0;
        *(uint4*)(sm + so + 16)          = va1;
        *(uint4*)(sm + TILE_B + so)      = vb0;
        *(uint4*)(sm + TILE_B + so + 16) = vb1;
    }
    __syncthreads();

    for (int ic = 0; ic < NCH; ic++) {
        const uint32_t cur = uBase + (uint32_t)((ic & 1) * STAGE_B);
        char* nxt = sm + ((ic + 1) & 1) * STAGE_B;

        // register prefetch for next chunk, in flight under the MMAs
        if (ic + 1 < NCH) {
            const char* as = (const char*)(arow + (ic + 1) * KC) + lhal * 32;
            const char* bs = (const char*)(brow + (ic + 1) * KC) + lhal * 32;
            va0 = *(const uint4*)as;  va1 = *(const uint4*)(as + 16);
            vb0 = *(const uint4*)bs;  vb1 = *(const uint4*)(bs + 16);
        }

        #pragma unroll
        for (int k16 = 0; k16 < 2; k16++) {
            uint32_t af[4][4];
            #pragma unroll
            for (int i = 0; i < 4; i++) {
                uint32_t ad = cur + (uint32_t)((wm * 64 + i * 16 + (lane & 15)) * PITCH
                                               + k16 * 32 + (lane >> 4) * 16);
                LDSM4(af[i], ad);
            }
            uint32_t bf[8];
            #pragma unroll
            for (int p = 0; p < 2; p++) {
                uint32_t bd = cur + (uint32_t)TILE_B
                            + (uint32_t)((wn * 32 + p * 16 + (lane & 7) + ((lane >> 4) << 3)) * PITCH
                                         + k16 * 32 + ((lane >> 3) & 1) * 16);
                LDSM4(&bf[p * 4], bd);
            }
            #pragma unroll
            for (int i = 0; i < 4; i++)
                #pragma unroll
                for (int j = 0; j < 4; j++)
                    mma_f16(acc[i][j], af[i], &bf[(j >> 1) * 4 + (j & 1) * 2]);
        }

        // stage next chunk into the other buffer; ONE barrier per chunk
        if (ic + 1 < NCH) {
            *(uint4*)(nxt + so)               = va0;
            *(uint4*)(nxt + so + 16)          = va1;
            *(uint4*)(nxt + TILE_B + so)      = vb0;
            *(uint4*)(nxt + TILE_B + so + 16) = vb1;
            __syncthreads();
        }
    }
    __syncthreads();   // buffers reusable by the caller's next pass
}

// ---------------- GEMM1 fused: h = silu(x@Wg^T) * (x@Wu^T), fp16 out --------
__global__ void __launch_bounds__(256, 1) k_gemm1() {
    constexpr int K = H_DIM;
    const int mt = blockIdx.y, nt = blockIdx.x;
    const int expert = g_tile_expert[mt];
    if (expert < 0) return;
    const __half* __restrict__ Wb = g_w1h + (size_t)expert * (2 * I_DIM) * K;

    extern __shared__ __align__(128) char sm[];
    float* stash = (float*)(sm + 2 * STAGE_B);

    const int tid = threadIdx.x, lane = tid & 31, wid = tid >> 5;
    const int wm = wid & 1, wn = wid >> 1;
    const int lrow = tid >> 1, lhal = tid & 1;

    int tok = g_slot_token[mt * BM + lrow];
    if (tok < 0) tok = 0;   // dead rows: finite values, results unused
    const __half* arow = g_xh + (size_t)tok * K;
    const __half* browG = Wb + (size_t)(nt * BN + lrow) * K;
    const __half* browU = Wb + (size_t)(I_DIM + nt * BN + lrow) * K;

    const uint32_t uBase = smem_u32(sm);
    float acc[4][4][4];

    #pragma unroll
    for (int i = 0; i < 4; i++)
        #pragma unroll
        for (int j = 0; j < 4; j++)
            #pragma unroll
            for (int q = 0; q < 4; q++) acc[i][j][q] = 0.f;
    gemm_pass<K>(arow, browG, sm, uBase, lrow, lhal, wm, wn, lane, acc);
    {
        float* st = stash + tid * 64;
        #pragma unroll
        for (int i = 0; i < 4; i++)
            #pragma unroll
            for (int j = 0; j < 4; j++)
                #pragma unroll
                for (int q = 0; q < 4; q++) st[(i * 4 + j) * 4 + q] = acc[i][j][q];
    }

    #pragma unroll
    for (int i = 0; i < 4; i++)
        #pragma unroll
        for (int j = 0; j < 4; j++)
            #pragma unroll
            for (int q = 0; q < 4; q++) acc[i][j][q] = 0.f;
    gemm_pass<K>(arow, browU, sm, uBase, lrow, lhal, wm, wn, lane, acc);

    // epilogue: h = silu(gate) * up -> g_h (fp16; same rounding point as R13)
    const int mrow = mt * BM + wm * 64;
    const int ncol = nt * BN + wn * 32;
    const float* st = stash + tid * 64;
    #pragma unroll
    for (int i = 0; i < 4; i++) {
        int r0 = mrow + i * 16 + (lane >> 2);
        #pragma unroll
        for (int j = 0; j < 4; j++) {
            int c0 = ncol + j * 8 + 2 * (lane & 3);
            float g0 = st[(i * 4 + j) * 4 + 0], g1 = st[(i * 4 + j) * 4 + 1];
            float g2 = st[(i * 4 + j) * 4 + 2], g3 = st[(i * 4 + j) * 4 + 3];
            float h0 = g0 / (1.f + __expf(-g0)) * acc[i][j][0];
            float h1 = g1 / (1.f + __expf(-g1)) * acc[i][j][1];
            float h2 = g2 / (1.f + __expf(-g2)) * acc[i][j][2];
            float h3 = g3 / (1.f + __expf(-g3)) * acc[i][j][3];
            *(__half2*)(g_h + (size_t)r0 * I_DIM + c0)       = __floats2half2_rn(h0, h1);
            *(__half2*)(g_h + (size_t)(r0 + 8) * I_DIM + c0) = __floats2half2_rn(h2, h3);
        }
    }
}

// ---------------- GEMM2: y = h @ w2s[e]^T -----------------------------------
__global__ void __launch_bounds__(256, 1) k_gemm2() {
    constexpr int K = I_DIM;
    const int mt = blockIdx.y, nt = blockIdx.x;
    const int expert = g_tile_expert[mt];
    if (expert < 0) return;
    const __half* __restrict__ Wb = g_w2h + (size_t)expert * H_DIM * K;

    extern __shared__ __align__(128) char sm[];

    const int tid = threadIdx.x, lane = tid & 31, wid = tid >> 5;
    const int wm = wid & 1, wn = wid >> 1;
    const int lrow = tid >> 1, lhal = tid & 1;

    const __half* arow = g_h + (size_t)(mt * BM + lrow) * K;
    const __half* brow = Wb + (size_t)(nt * BN + lrow) * K;

    const uint32_t uBase = smem_u32(sm);
    float acc[4][4][4];
    #pragma unroll
    for (int i = 0; i < 4; i++)
        #pragma unroll
        for (int j = 0; j < 4; j++)
            #pragma unroll
            for (int q = 0; q < 4; q++) acc[i][j][q] = 0.f;
    gemm_pass<K>(arow, brow, sm, uBase, lrow, lhal, wm, wn, lane, acc);

    const int mrow = mt * BM + wm * 64;
    const int ncol = nt * BN + wn * 32;
    #pragma unroll
    for (int i = 0; i < 4; i++) {
        int r0 = mrow + i * 16 + (lane >> 2);
        #pragma unroll
        for (int j = 0; j < 4; j++) {
            int c0 = ncol + j * 8 + 2 * (lane & 3);
            float* p0 = g_y + (size_t)r0 * H_DIM + c0;
            p0[0] = acc[i][j][0];
            p0[1] = acc[i][j][1];
            float* p1 = p0 + (size_t)8 * H_DIM;
            p1[0] = acc[i][j][2];
            p1[1] = acc[i][j][3];
        }
    }
}

// ---------------- combine ---------------------------------------------------
__global__ void k_combine(float* __restrict__ out) {
    int idx = blockIdx.x * blockDim.x + threadIdx.x;
    if (idx >= T_TOK * (H_DIM / 4)) return;
    int t = idx / (H_DIM / 4);
    int n = (idx % (H_DIM / 4)) * 4;
    int   s0 = g_tok_slot[t * 2 + 0], s1 = g_tok_slot[t * 2 + 1];
    float w0 = g_tok_w [t * 2 + 0], w1 = g_tok_w [t * 2 + 1];
    const float4 y0 = *(const float4*)&g_y[(size_t)s0 * H_DIM + n];
    const float4 y1 = *(const float4*)&g_y[(size_t)s1 * H_DIM + n];
    float4 o;
    o.x = w0 * y0.x + w1 * y1.x;
    o.y = w0 * y0.y + w1 * y1.y;
    o.z = w0 * y0.z + w1 * y1.z;
    o.w = w0 * y0.w + w1 * y1.w;
    *(float4*)&out[(size_t)t * H_DIM + n] = o;
}

// ---------------- launch ----------------------------------------------------
extern "C" void kernel_launch(void* const* d_in, const int* in_sizes, int n_in,
                              void* d_out, int out_size) {
    const float* x      = (const float*)d_in[0];
    const float* gate_w = (const float*)d_in[1];
    const float* ws     = (const float*)d_in[2];
    const float* w2s    = (const float*)d_in[3];
    float* out = (float*)d_out;

    cudaFuncSetAttribute(k_gemm1, cudaFuncAttributeMaxDynamicSharedMemorySize, DYN1);
    cudaFuncSetAttribute(k_gemm2, cudaFuncAttributeMaxDynamicSharedMemorySize, DYN2);

    k_init<<<(MAX_SLOTS + 255) / 256, 256>>>();
    k_route<<<T_TOK, 512>>>(x, gate_w);
    k_offsets<<<1, 32>>>();
    k_scatter<<<(T_TOK + 255) / 256, 256>>>();

    // fp32 -> fp16 pre-conversion (bandwidth-bound)
    {
        int n8x = (T_TOK * H_DIM) / 8;
        int n8w = (E_NUM * 2 * I_DIM * H_DIM) / 8;
        int n8v = (E_NUM * H_DIM * I_DIM) / 8;
        k_cvt<<<(n8x + 255) / 256, 256>>>(x, 0, n8x);
        k_cvt<<<(n8w + 255) / 256, 256>>>(ws, 1, n8w);
        k_cvt<<<(n8v + 255) / 256, 256>>>(w2s, 2, n8v);
    }

    k_gemm1<<<dim3(I_DIM / BN, M_TILES), 256, DYN1>>>();
    k_gemm2<<<dim3(H_DIM / BN, M_TILES), 256, DYN2>>>();
    k_combine<<<(T_TOK * (H_DIM / 4) + 255) / 256, 256>>>(out);
}